// round 3
// baseline (speedup 1.0000x reference)
#include <cuda_runtime.h>

// ---------------------------------------------------------------------------
// Problem constants
// ---------------------------------------------------------------------------
#define B_    32
#define N_    512
#define OBJ   2048
#define QD    1024
#define CD    (OBJ + QD)      // 3072
#define MTOT  (B_ * N_)       // 16384
#define STOT  ((size_t)B_ * N_ * N_)   // 8388608

// ---------------------------------------------------------------------------
// Device scratch (static allocation -> allowed; no runtime mallocs)
// ---------------------------------------------------------------------------
__device__ __align__(16) float g_W1[QD * CD];              // 12 MB  weight-normed W1
__device__ __align__(16) float g_W2[QD * QD];              // 4 MB   weight-normed W2
__device__ __align__(16) float g_qterm[B_ * QD];           // per-batch q contribution + b1
__device__ __align__(16) float g_h1[(size_t)MTOT * QD];    // 64 MB
__device__ __align__(16) float g_h2[(size_t)MTOT * QD];    // 64 MB
__device__ __align__(16) float g_S[STOT];                  // 33.5 MB edge logits
__device__ unsigned int g_odd_or;                          // dtype-detection accumulator

// ---------------------------------------------------------------------------
// Index-dtype detection: indexes may be int32 (JAX x64 disabled) or int64.
// Values are < 2^23, so if the buffer is int64 every odd 32-bit word of the
// first E words is zero. OR of odd words == 0  =>  int64 layout.
// ---------------------------------------------------------------------------
__global__ void zero_flag_kernel() { g_odd_or = 0u; }

__global__ void detect_kernel(const unsigned int* __restrict__ w, int n_words) {
    int i = blockIdx.x * blockDim.x + threadIdx.x;
    unsigned int v = 0u;
    // stride over odd positions only
    for (int p = 2 * i + 1; p < n_words; p += 2 * gridDim.x * blockDim.x) v |= w[p];
    // warp-reduce then one atomic per warp
    for (int o = 16; o; o >>= 1) v |= __shfl_down_sync(0xFFFFFFFFu, v, o);
    if ((threadIdx.x & 31) == 0 && v) atomicOr(&g_odd_or, v);
}

// ---------------------------------------------------------------------------
// Kernel 0: weight norm for both layers.
// ---------------------------------------------------------------------------
__global__ void wn_kernel(const float* __restrict__ v1, const float* __restrict__ g1,
                          const float* __restrict__ v2, const float* __restrict__ g2) {
    int r = blockIdx.x;
    const float* src;
    float* dst;
    int len;
    float g;
    if (r < QD) { src = v1 + (size_t)r * CD; dst = g_W1 + (size_t)r * CD; len = CD; g = g1[r]; }
    else        { int rr = r - QD; src = v2 + (size_t)rr * QD; dst = g_W2 + (size_t)rr * QD; len = QD; g = g2[rr]; }

    float s = 0.f;
    for (int i = threadIdx.x; i < len; i += blockDim.x) { float x = src[i]; s += x * x; }

    __shared__ float red[32];
    for (int o = 16; o; o >>= 1) s += __shfl_down_sync(0xFFFFFFFFu, s, o);
    if ((threadIdx.x & 31) == 0) red[threadIdx.x >> 5] = s;
    __syncthreads();
    if (threadIdx.x < 32) {
        float t = (threadIdx.x < (blockDim.x >> 5)) ? red[threadIdx.x] : 0.f;
        for (int o = 16; o; o >>= 1) t += __shfl_down_sync(0xFFFFFFFFu, t, o);
        if (threadIdx.x == 0) red[0] = rsqrtf(t);
    }
    __syncthreads();
    float scale = g * red[0];
    for (int i = threadIdx.x; i < len; i += blockDim.x) dst[i] = src[i] * scale;
}

// ---------------------------------------------------------------------------
// Kernel 1: qterm[b, d] = b1[d] + sum_c q_feats[b, c] * W1[d, OBJ + c]
// ---------------------------------------------------------------------------
__global__ void qterm_kernel(const float* __restrict__ q_feats, const float* __restrict__ b1) {
    __shared__ __align__(16) float q[QD];
    int b = blockIdx.y;
    for (int i = threadIdx.x; i < QD; i += blockDim.x) q[i] = q_feats[(size_t)b * QD + i];
    __syncthreads();
    int d = blockIdx.x * blockDim.x + threadIdx.x;
    const float* w = g_W1 + (size_t)d * CD + OBJ;
    float s = b1[d];
#pragma unroll 8
    for (int c = 0; c < QD; c++) s = fmaf(q[c], w[c], s);
    g_qterm[(size_t)b * QD + d] = s;
}

// ---------------------------------------------------------------------------
// Tiled NT SGEMM: C[m,n] = sum_k A[m,k] * B[n,k]
// MODE 1: A=node_feats, B=g_W1[:, :OBJ], C=g_h1, epi: +qterm, ReLU
// MODE 2: A=g_h1, B=g_W2, C=g_h2, epi: +b2, ReLU
// MODE 0: per-batch: A=B=g_h2[z], C=g_S[z]
// ---------------------------------------------------------------------------
template <int MODE>
__global__ void __launch_bounds__(256, 2) sgemm_nt(const float* __restrict__ Aext,
                                                   const float* __restrict__ biasext) {
    constexpr int BM = 128, BN = 128, BK = 16, PAD = 4;
    constexpr int K   = (MODE == 1) ? OBJ : QD;
    constexpr int lda = (MODE == 1) ? OBJ : QD;
    constexpr int ldb = (MODE == 1) ? CD  : QD;
    constexpr int ldc = (MODE == 0) ? N_  : QD;

    __shared__ __align__(16) float As[BK][BM + PAD];
    __shared__ __align__(16) float Bs[BK][BN + PAD];

    const float* A;
    const float* Bm;
    float* C;
    if (MODE == 1)      { A = Aext;  Bm = g_W1; C = g_h1; }
    else if (MODE == 2) { A = g_h1;  Bm = g_W2; C = g_h2; }
    else {
        size_t off = (size_t)blockIdx.z * ((size_t)N_ * QD);
        A  = g_h2 + off;
        Bm = g_h2 + off;
        C  = g_S + (size_t)blockIdx.z * ((size_t)N_ * N_);
    }

    const int tid = threadIdx.x;
    const int tx = tid & 15, ty = tid >> 4;

    const float* Ag = A  + (size_t)(blockIdx.y * BM) * lda;
    const float* Bg = Bm + (size_t)(blockIdx.x * BN) * ldb;

    const int r0  = tid >> 2;
    const int r1  = r0 + 64;
    const int kq  = (tid & 3) * 4;

    float acc[8][8];
#pragma unroll
    for (int i = 0; i < 8; i++)
#pragma unroll
        for (int j = 0; j < 8; j++) acc[i][j] = 0.f;

    float4 va0 = *(const float4*)(Ag + (size_t)r0 * lda + kq);
    float4 va1 = *(const float4*)(Ag + (size_t)r1 * lda + kq);
    float4 vb0 = *(const float4*)(Bg + (size_t)r0 * ldb + kq);
    float4 vb1 = *(const float4*)(Bg + (size_t)r1 * ldb + kq);

    for (int k0 = 0; k0 < K; k0 += BK) {
        As[kq + 0][r0] = va0.x; As[kq + 1][r0] = va0.y; As[kq + 2][r0] = va0.z; As[kq + 3][r0] = va0.w;
        As[kq + 0][r1] = va1.x; As[kq + 1][r1] = va1.y; As[kq + 2][r1] = va1.z; As[kq + 3][r1] = va1.w;
        Bs[kq + 0][r0] = vb0.x; Bs[kq + 1][r0] = vb0.y; Bs[kq + 2][r0] = vb0.z; Bs[kq + 3][r0] = vb0.w;
        Bs[kq + 0][r1] = vb1.x; Bs[kq + 1][r1] = vb1.y; Bs[kq + 2][r1] = vb1.z; Bs[kq + 3][r1] = vb1.w;
        __syncthreads();

        if (k0 + BK < K) {
            int kn = k0 + BK + kq;
            va0 = *(const float4*)(Ag + (size_t)r0 * lda + kn);
            va1 = *(const float4*)(Ag + (size_t)r1 * lda + kn);
            vb0 = *(const float4*)(Bg + (size_t)r0 * ldb + kn);
            vb1 = *(const float4*)(Bg + (size_t)r1 * ldb + kn);
        }

#pragma unroll
        for (int k = 0; k < BK; k++) {
            float a[8], b[8];
            *(float4*)(a)     = *(const float4*)(&As[k][ty * 8]);
            *(float4*)(a + 4) = *(const float4*)(&As[k][ty * 8 + 4]);
            *(float4*)(b)     = *(const float4*)(&Bs[k][tx * 8]);
            *(float4*)(b + 4) = *(const float4*)(&Bs[k][tx * 8 + 4]);
#pragma unroll
            for (int i = 0; i < 8; i++)
#pragma unroll
                for (int j = 0; j < 8; j++) acc[i][j] = fmaf(a[i], b[j], acc[i][j]);
        }
        __syncthreads();
    }

    const int row0 = blockIdx.y * BM + ty * 8;
    const int col0 = blockIdx.x * BN + tx * 8;
#pragma unroll
    for (int i = 0; i < 8; i++) {
        int row = row0 + i;
        float* crow = C + (size_t)row * ldc + col0;
#pragma unroll
        for (int j = 0; j < 8; j++) {
            float v = acc[i][j];
            if (MODE == 1)      v = fmaxf(v + g_qterm[(size_t)(row >> 9) * QD + col0 + j], 0.f);
            else if (MODE == 2) v = fmaxf(v + biasext[col0 + j], 0.f);
            crow[j] = v;
        }
    }
}

// ---------------------------------------------------------------------------
// Gather: dtype decided by detection flag. Index clamped so a wrong branch
// shows up as rel_err, never as an illegal access.
// ---------------------------------------------------------------------------
__global__ void gather_kernel(const void* __restrict__ idx, float* __restrict__ out, int n) {
    int e = blockIdx.x * blockDim.x + threadIdx.x;
    if (e >= n) return;
    bool is64 = (g_odd_or == 0u);
    long long v = is64 ? ((const long long*)idx)[e] : (long long)((const int*)idx)[e];
    if (v < 0) v = 0;
    if (v >= (long long)STOT) v = (long long)STOT - 1;
    out[e] = g_S[v];
}

// ---------------------------------------------------------------------------
// Host entry (graph-capturable: kernel launches only, default stream)
// ---------------------------------------------------------------------------
extern "C" void kernel_launch(void* const* d_in, const int* in_sizes, int n_in,
                              void* d_out, int out_size) {
    const float* node = (const float*)d_in[0];
    const float* qf   = (const float*)d_in[1];
    const void*  idx  = d_in[2];
    const float* v1   = (const float*)d_in[3];
    const float* g1   = (const float*)d_in[4];
    const float* b1   = (const float*)d_in[5];
    const float* v2   = (const float*)d_in[6];
    const float* g2   = (const float*)d_in[7];
    const float* b2   = (const float*)d_in[8];
    float*       out  = (float*)d_out;

    (void)n_in;

    // 0) index dtype detection (reads only E 32-bit words — safe either way)
    zero_flag_kernel<<<1, 1>>>();
    detect_kernel<<<128, 256>>>((const unsigned int*)idx, out_size);

    // 1) weight norm for W1 and W2
    wn_kernel<<<2 * QD, 256>>>(v1, g1, v2, g2);

    // 2) per-batch q contribution folded into a [B, QD] bias
    qterm_kernel<<<dim3(QD / 256, B_), 256>>>(qf, b1);

    // 3) h1 = relu(node @ W1a^T + qterm)
    sgemm_nt<1><<<dim3(QD / 128, MTOT / 128), 256>>>(node, nullptr);

    // 4) h2 = relu(h1 @ W2^T + b2)
    sgemm_nt<2><<<dim3(QD / 128, MTOT / 128), 256>>>(nullptr, b2);

    // 5) S[b] = h2[b] @ h2[b]^T
    sgemm_nt<0><<<dim3(N_ / 128, N_ / 128, B_), 256>>>(nullptr, nullptr);

    // 6) gather requested edges
    gather_kernel<<<(out_size + 255) / 256, 256>>>(idx, out, out_size);
}

// round 4
// speedup vs baseline: 1.2558x; 1.2558x over previous
#include <cuda_runtime.h>
#include <cstdint>

// ---------------------------------------------------------------------------
// Problem constants
// ---------------------------------------------------------------------------
#define B_    32
#define N_    512
#define OBJ   2048
#define QD    1024
#define CD    (OBJ + QD)      // 3072
#define MTOT  (B_ * N_)       // 16384
#define STOT  ((size_t)B_ * N_ * N_)   // 8388608

// ---------------------------------------------------------------------------
// Device scratch
// ---------------------------------------------------------------------------
__device__ __align__(16) float g_W1[QD * CD];              // weight-normed W1
__device__ __align__(16) float g_W2[QD * QD];              // weight-normed W2
__device__ __align__(16) float g_qterm[B_ * QD];           // q contribution + b1
__device__ __align__(16) float g_h1[(size_t)MTOT * QD];
__device__ __align__(16) float g_h2[(size_t)MTOT * QD];
__device__ __align__(16) float g_S[STOT];
__device__ unsigned int g_odd_or;

// ---------------------------------------------------------------------------
// helpers
// ---------------------------------------------------------------------------
__device__ __forceinline__ uint32_t f2tf32(float x) {
    uint32_t r;
    asm("cvt.rna.tf32.f32 %0, %1;" : "=r"(r) : "f"(x));
    return r;
}

__device__ __forceinline__ void mma_tf32(float* c, const uint32_t* a, const uint32_t* b) {
    asm volatile(
        "mma.sync.aligned.m16n8k8.row.col.f32.tf32.tf32.f32 "
        "{%0,%1,%2,%3}, {%4,%5,%6,%7}, {%8,%9}, {%0,%1,%2,%3};"
        : "+f"(c[0]), "+f"(c[1]), "+f"(c[2]), "+f"(c[3])
        : "r"(a[0]), "r"(a[1]), "r"(a[2]), "r"(a[3]), "r"(b[0]), "r"(b[1]));
}

// ---------------------------------------------------------------------------
// Index-dtype detection (indexes may be int32 or int64; values < 2^23)
// ---------------------------------------------------------------------------
__global__ void zero_flag_kernel() { g_odd_or = 0u; }

__global__ void detect_kernel(const unsigned int* __restrict__ w, int n_words) {
    int i = blockIdx.x * blockDim.x + threadIdx.x;
    unsigned int v = 0u;
    for (int p = 2 * i + 1; p < n_words; p += 2 * gridDim.x * blockDim.x) v |= w[p];
    for (int o = 16; o; o >>= 1) v |= __shfl_down_sync(0xFFFFFFFFu, v, o);
    if ((threadIdx.x & 31) == 0 && v) atomicOr(&g_odd_or, v);
}

// ---------------------------------------------------------------------------
// Weight norm for both layers
// ---------------------------------------------------------------------------
__global__ void wn_kernel(const float* __restrict__ v1, const float* __restrict__ g1,
                          const float* __restrict__ v2, const float* __restrict__ g2) {
    int r = blockIdx.x;
    const float* src;
    float* dst;
    int len;
    float g;
    if (r < QD) { src = v1 + (size_t)r * CD; dst = g_W1 + (size_t)r * CD; len = CD; g = g1[r]; }
    else        { int rr = r - QD; src = v2 + (size_t)rr * QD; dst = g_W2 + (size_t)rr * QD; len = QD; g = g2[rr]; }

    float s = 0.f;
    for (int i = threadIdx.x; i < len; i += blockDim.x) { float x = src[i]; s += x * x; }

    __shared__ float red[32];
    for (int o = 16; o; o >>= 1) s += __shfl_down_sync(0xFFFFFFFFu, s, o);
    if ((threadIdx.x & 31) == 0) red[threadIdx.x >> 5] = s;
    __syncthreads();
    if (threadIdx.x < 32) {
        float t = (threadIdx.x < (blockDim.x >> 5)) ? red[threadIdx.x] : 0.f;
        for (int o = 16; o; o >>= 1) t += __shfl_down_sync(0xFFFFFFFFu, t, o);
        if (threadIdx.x == 0) red[0] = rsqrtf(t);
    }
    __syncthreads();
    float scale = g * red[0];
    for (int i = threadIdx.x; i < len; i += blockDim.x) dst[i] = src[i] * scale;
}

// ---------------------------------------------------------------------------
// qterm[b, d] = b1[d] + sum_c q_feats[b, c] * W1[d, OBJ + c]
// One block per d; W1 row staged coalesced in smem; warps split batches.
// ---------------------------------------------------------------------------
__global__ void qterm_kernel(const float* __restrict__ q_feats, const float* __restrict__ b1) {
    __shared__ __align__(16) float w[QD];
    int d = blockIdx.x;
    for (int i = threadIdx.x; i < QD; i += blockDim.x) w[i] = g_W1[(size_t)d * CD + OBJ + i];
    __syncthreads();
    int wid = threadIdx.x >> 5, lane = threadIdx.x & 31;
    float bias = b1[d];
    for (int b = wid; b < B_; b += 8) {
        const float* q = q_feats + (size_t)b * QD;
        float s = 0.f;
        for (int c = lane; c < QD; c += 32) s = fmaf(w[c], q[c], s);
        for (int o = 16; o; o >>= 1) s += __shfl_down_sync(0xFFFFFFFFu, s, o);
        if (lane == 0) g_qterm[(size_t)b * QD + d] = s + bias;
    }
}

// ---------------------------------------------------------------------------
// TF32 tensor-core NT GEMM: C[m,n] = sum_k A[m,k] * B[n,k]
// MODE 1: A=node_feats, B=g_W1[:, :OBJ], C=g_h1, epi: +qterm[batch], ReLU
// MODE 2: A=g_h1, B=g_W2, C=g_h2, epi: +b2, ReLU
// MODE 0: per-batch z: A=B=g_h2[z], C=g_S[z]
// 128x128x32 tiles, 256 thr, warp grid 2(M)x4(N), m16n8k8 tf32 mma.
// ---------------------------------------------------------------------------
template <int MODE>
__global__ void __launch_bounds__(256, 1) tgemm(const float* __restrict__ Aext,
                                                const float* __restrict__ biasext) {
    constexpr int BM = 128, BN = 128, BK = 32;
    constexpr int KP  = BK + 4;     // smem row stride (words); 16B-aligned rows
    constexpr int K   = (MODE == 1) ? OBJ : QD;
    constexpr int lda = (MODE == 1) ? OBJ : QD;
    constexpr int ldb = (MODE == 1) ? CD  : QD;
    constexpr int ldc = (MODE == 0) ? N_  : QD;

    __shared__ __align__(16) uint32_t As[BM * KP];
    __shared__ __align__(16) uint32_t Bs[BN * KP];

    const float* A;
    const float* Bm;
    float* C;
    if (MODE == 1)      { A = Aext; Bm = g_W1; C = g_h1; }
    else if (MODE == 2) { A = g_h1; Bm = g_W2; C = g_h2; }
    else {
        size_t off = (size_t)blockIdx.z * ((size_t)N_ * QD);
        A = g_h2 + off; Bm = g_h2 + off;
        C = g_S + (size_t)blockIdx.z * ((size_t)N_ * N_);
    }

    const int tid  = threadIdx.x;
    const int wid  = tid >> 5;
    const int lane = tid & 31;
    const int wm   = wid >> 2;          // 0..1   (64 rows each)
    const int wn   = wid & 3;           // 0..3   (32 cols each)
    const int gr   = lane >> 2;         // 0..7
    const int ct   = lane & 3;          // 0..3

    // global tile load mapping: thread -> row tid>>1, 16 consecutive k floats
    const int lrow = tid >> 1;
    const int lk   = (tid & 1) * 16;

    const float* Ag = A  + (size_t)(blockIdx.y * BM + lrow) * lda + lk;
    const float* Bg = Bm + (size_t)(blockIdx.x * BN + lrow) * ldb + lk;

    float acc[4][4][4];
#pragma unroll
    for (int i = 0; i < 4; i++)
#pragma unroll
        for (int j = 0; j < 4; j++)
#pragma unroll
            for (int r = 0; r < 4; r++) acc[i][j][r] = 0.f;

    // prefetch first tile
    float4 pa[4], pb[4];
#pragma unroll
    for (int i = 0; i < 4; i++) {
        pa[i] = *(const float4*)(Ag + i * 4);
        pb[i] = *(const float4*)(Bg + i * 4);
    }

    for (int k0 = 0; k0 < K; k0 += BK) {
        // commit prefetched tile to smem (convert fp32 -> tf32 once here)
        uint32_t* as = &As[lrow * KP + lk];
        uint32_t* bs = &Bs[lrow * KP + lk];
#pragma unroll
        for (int i = 0; i < 4; i++) {
            uint4 ua = { f2tf32(pa[i].x), f2tf32(pa[i].y), f2tf32(pa[i].z), f2tf32(pa[i].w) };
            uint4 ub = { f2tf32(pb[i].x), f2tf32(pb[i].y), f2tf32(pb[i].z), f2tf32(pb[i].w) };
            *(uint4*)(as + i * 4) = ua;
            *(uint4*)(bs + i * 4) = ub;
        }
        __syncthreads();

        // prefetch next tile (overlaps mma below)
        if (k0 + BK < K) {
#pragma unroll
            for (int i = 0; i < 4; i++) {
                pa[i] = *(const float4*)(Ag + k0 + BK + i * 4);
                pb[i] = *(const float4*)(Bg + k0 + BK + i * 4);
            }
        }

#pragma unroll
        for (int ks = 0; ks < 4; ks++) {
            const int kb = ks * 8;
            uint32_t af[4][4], bf[4][2];
#pragma unroll
            for (int mt = 0; mt < 4; mt++) {
                const uint32_t* base = &As[(wm * 64 + mt * 16 + gr) * KP + kb + ct];
                af[mt][0] = base[0];
                af[mt][1] = base[8 * KP];
                af[mt][2] = base[4];
                af[mt][3] = base[8 * KP + 4];
            }
#pragma unroll
            for (int nt = 0; nt < 4; nt++) {
                const uint32_t* base = &Bs[(wn * 32 + nt * 8 + gr) * KP + kb + ct];
                bf[nt][0] = base[0];
                bf[nt][1] = base[4];
            }
#pragma unroll
            for (int mt = 0; mt < 4; mt++)
#pragma unroll
                for (int nt = 0; nt < 4; nt++)
                    mma_tf32(acc[mt][nt], af[mt], bf[nt]);
        }
        __syncthreads();
    }

    // epilogue
    const int batch_base = (MODE == 1) ? ((blockIdx.y * BM) >> 9) * QD : 0;
#pragma unroll
    for (int mt = 0; mt < 4; mt++) {
        int row_a = blockIdx.y * BM + wm * 64 + mt * 16 + gr;
#pragma unroll
        for (int nt = 0; nt < 4; nt++) {
            int col = blockIdx.x * BN + wn * 32 + nt * 8 + 2 * ct;
            float* c0 = C + (size_t)row_a * ldc + col;
            float* c1 = C + (size_t)(row_a + 8) * ldc + col;
            float2 v0 = { acc[mt][nt][0], acc[mt][nt][1] };
            float2 v1 = { acc[mt][nt][2], acc[mt][nt][3] };
            if (MODE == 1) {
                float b0 = g_qterm[batch_base + col];
                float b1v = g_qterm[batch_base + col + 1];
                v0.x = fmaxf(v0.x + b0, 0.f);  v0.y = fmaxf(v0.y + b1v, 0.f);
                v1.x = fmaxf(v1.x + b0, 0.f);  v1.y = fmaxf(v1.y + b1v, 0.f);
            } else if (MODE == 2) {
                float b0 = biasext[col];
                float b1v = biasext[col + 1];
                v0.x = fmaxf(v0.x + b0, 0.f);  v0.y = fmaxf(v0.y + b1v, 0.f);
                v1.x = fmaxf(v1.x + b0, 0.f);  v1.y = fmaxf(v1.y + b1v, 0.f);
            }
            *(float2*)c0 = v0;
            *(float2*)c1 = v1;
        }
    }
}

// ---------------------------------------------------------------------------
// Gather (dtype decided at runtime; clamped so mistakes show as rel_err)
// ---------------------------------------------------------------------------
__global__ void gather_kernel(const void* __restrict__ idx, float* __restrict__ out, int n) {
    int e = blockIdx.x * blockDim.x + threadIdx.x;
    if (e >= n) return;
    bool is64 = (g_odd_or == 0u);
    long long v = is64 ? ((const long long*)idx)[e] : (long long)((const int*)idx)[e];
    if (v < 0) v = 0;
    if (v >= (long long)STOT) v = (long long)STOT - 1;
    out[e] = g_S[v];
}

// ---------------------------------------------------------------------------
// Host entry (graph-capturable)
// ---------------------------------------------------------------------------
extern "C" void kernel_launch(void* const* d_in, const int* in_sizes, int n_in,
                              void* d_out, int out_size) {
    const float* node = (const float*)d_in[0];
    const float* qf   = (const float*)d_in[1];
    const void*  idx  = d_in[2];
    const float* v1   = (const float*)d_in[3];
    const float* g1   = (const float*)d_in[4];
    const float* b1   = (const float*)d_in[5];
    const float* v2   = (const float*)d_in[6];
    const float* g2   = (const float*)d_in[7];
    const float* b2   = (const float*)d_in[8];
    float*       out  = (float*)d_out;

    (void)n_in; (void)in_sizes;

    zero_flag_kernel<<<1, 1>>>();
    detect_kernel<<<128, 256>>>((const unsigned int*)idx, out_size);

    wn_kernel<<<2 * QD, 256>>>(v1, g1, v2, g2);
    qterm_kernel<<<QD, 256>>>(qf, b1);

    // h1 = relu(node @ W1a^T + qterm)
    tgemm<1><<<dim3(QD / 128, MTOT / 128), 256>>>(node, nullptr);
    // h2 = relu(h1 @ W2^T + b2)
    tgemm<2><<<dim3(QD / 128, MTOT / 128), 256>>>(nullptr, b2);
    // S[b] = h2[b] @ h2[b]^T
    tgemm<0><<<dim3(N_ / 128, N_ / 128, B_), 256>>>(nullptr, nullptr);

    gather_kernel<<<(out_size + 255) / 256, 256>>>(idx, out, out_size);
}

// round 6
// speedup vs baseline: 1.9145x; 1.5245x over previous
#include <cuda_runtime.h>
#include <cuda_bf16.h>
#include <cstdint>

// ---------------------------------------------------------------------------
// Problem constants
// ---------------------------------------------------------------------------
#define B_    32
#define N_    512
#define OBJ   2048
#define QD    1024
#define CD    3072
#define MTOT  16384
#define STOT  ((size_t)B_ * N_ * N_)

// ---------------------------------------------------------------------------
// Device scratch (static; no runtime allocation)
// ---------------------------------------------------------------------------
__device__ __align__(16) __nv_bfloat16 g_W1hi[(size_t)QD * OBJ];
__device__ __align__(16) __nv_bfloat16 g_W1lo[(size_t)QD * OBJ];
__device__ __align__(16) float         g_W1q [(size_t)QD * QD];
__device__ __align__(16) __nv_bfloat16 g_W2hi[(size_t)QD * QD];
__device__ __align__(16) __nv_bfloat16 g_W2lo[(size_t)QD * QD];
__device__ __align__(16) __nv_bfloat16 g_nhi [(size_t)MTOT * OBJ];
__device__ __align__(16) __nv_bfloat16 g_nlo [(size_t)MTOT * OBJ];
__device__ __align__(16) __nv_bfloat16 g_h1hi[(size_t)MTOT * QD];
__device__ __align__(16) __nv_bfloat16 g_h1lo[(size_t)MTOT * QD];
__device__ __align__(16) __nv_bfloat16 g_h2hi[(size_t)MTOT * QD];
__device__ __align__(16) __nv_bfloat16 g_h2lo[(size_t)MTOT * QD];
__device__ __align__(16) float g_S[STOT];
__device__ __align__(16) float g_qterm[B_ * QD];
__device__ unsigned int g_odd_or;

// ---------------------------------------------------------------------------
// helpers
// ---------------------------------------------------------------------------
__device__ __forceinline__ uint32_t smem_u32(const void* p) {
    uint32_t a;
    asm("{ .reg .u64 t; cvta.to.shared.u64 t, %1; cvt.u32.u64 %0, t; }" : "=r"(a) : "l"(p));
    return a;
}

__device__ __forceinline__ void cp16(uint32_t dst, const void* src) {
    asm volatile("cp.async.ca.shared.global [%0], [%1], 16;" :: "r"(dst), "l"(src) : "memory");
}
__device__ __forceinline__ void cp_commit() {
    asm volatile("cp.async.commit_group;" ::: "memory");
}
template <int N>
__device__ __forceinline__ void cp_wait() {
    asm volatile("cp.async.wait_group %0;" :: "n"(N) : "memory");
}

__device__ __forceinline__ void ldsm4(uint32_t* r, uint32_t addr) {
    asm volatile("ldmatrix.sync.aligned.m8n8.x4.shared.b16 {%0,%1,%2,%3}, [%4];"
                 : "=r"(r[0]), "=r"(r[1]), "=r"(r[2]), "=r"(r[3]) : "r"(addr));
}

__device__ __forceinline__ void mma_bf16(float* c, const uint32_t* a, const uint32_t* b) {
    asm volatile(
        "mma.sync.aligned.m16n8k16.row.col.f32.bf16.bf16.f32 "
        "{%0,%1,%2,%3}, {%4,%5,%6,%7}, {%8,%9}, {%0,%1,%2,%3};"
        : "+f"(c[0]), "+f"(c[1]), "+f"(c[2]), "+f"(c[3])
        : "r"(a[0]), "r"(a[1]), "r"(a[2]), "r"(a[3]), "r"(b[0]), "r"(b[1]));
}

// pack two floats to bf16x2 word (first arg -> low half)
__device__ __forceinline__ uint32_t packbf(float lo_elem, float hi_elem) {
    uint32_t w;
    asm("cvt.rn.bf16x2.f32 %0, %1, %2;" : "=r"(w) : "f"(hi_elem), "f"(lo_elem));
    return w;
}

// ---------------------------------------------------------------------------
// Index-dtype detection (indexes may be int32 or int64; values < 2^23)
// ---------------------------------------------------------------------------
__global__ void zero_flag_kernel() { g_odd_or = 0u; }

__global__ void detect_kernel(const unsigned int* __restrict__ w, int n_words) {
    int i = blockIdx.x * blockDim.x + threadIdx.x;
    unsigned int v = 0u;
    for (int p = 2 * i + 1; p < n_words; p += 2 * gridDim.x * blockDim.x) v |= w[p];
    for (int o = 16; o; o >>= 1) v |= __shfl_down_sync(0xFFFFFFFFu, v, o);
    if ((threadIdx.x & 31) == 0 && v) atomicOr(&g_odd_or, v);
}

// ---------------------------------------------------------------------------
// Weight norm -> bf16 hi/lo (node part) + fp32 (q part of W1)
// ---------------------------------------------------------------------------
__global__ void wn_kernel(const float* __restrict__ v1, const float* __restrict__ g1,
                          const float* __restrict__ v2, const float* __restrict__ g2) {
    int r = blockIdx.x;
    const float* src;
    int len;
    float g;
    if (r < QD) { src = v1 + (size_t)r * CD; len = CD; g = g1[r]; }
    else        { src = v2 + (size_t)(r - QD) * QD; len = QD; g = g2[r - QD]; }

    float s = 0.f;
    for (int i = threadIdx.x; i < len; i += blockDim.x) { float x = src[i]; s += x * x; }

    __shared__ float red[32];
    for (int o = 16; o; o >>= 1) s += __shfl_down_sync(0xFFFFFFFFu, s, o);
    if ((threadIdx.x & 31) == 0) red[threadIdx.x >> 5] = s;
    __syncthreads();
    if (threadIdx.x < 32) {
        float t = (threadIdx.x < (blockDim.x >> 5)) ? red[threadIdx.x] : 0.f;
        for (int o = 16; o; o >>= 1) t += __shfl_down_sync(0xFFFFFFFFu, t, o);
        if (threadIdx.x == 0) red[0] = rsqrtf(t);
    }
    __syncthreads();
    float scale = g * red[0];

    if (r < QD) {
        for (int i = threadIdx.x; i < CD; i += blockDim.x) {
            float x = src[i] * scale;
            if (i < OBJ) {
                __nv_bfloat16 h = __float2bfloat16(x);
                g_W1hi[(size_t)r * OBJ + i] = h;
                g_W1lo[(size_t)r * OBJ + i] = __float2bfloat16(x - __bfloat162float(h));
            } else {
                g_W1q[(size_t)r * QD + (i - OBJ)] = x;
            }
        }
    } else {
        int rr = r - QD;
        for (int i = threadIdx.x; i < QD; i += blockDim.x) {
            float x = src[i] * scale;
            __nv_bfloat16 h = __float2bfloat16(x);
            g_W2hi[(size_t)rr * QD + i] = h;
            g_W2lo[(size_t)rr * QD + i] = __float2bfloat16(x - __bfloat162float(h));
        }
    }
}

// ---------------------------------------------------------------------------
// node_feats fp32 -> bf16 hi/lo split
// ---------------------------------------------------------------------------
__global__ void node_cvt_kernel(const float* __restrict__ node) {
    size_t i4 = (size_t)blockIdx.x * blockDim.x + threadIdx.x;
    float4 v = *(const float4*)(node + i4 * 4);
    __nv_bfloat16 h0 = __float2bfloat16(v.x), h1 = __float2bfloat16(v.y);
    __nv_bfloat16 h2 = __float2bfloat16(v.z), h3 = __float2bfloat16(v.w);
    float l0 = v.x - __bfloat162float(h0), l1 = v.y - __bfloat162float(h1);
    float l2 = v.z - __bfloat162float(h2), l3 = v.w - __bfloat162float(h3);
    uint2 hw, lw;
    hw.x = packbf(__bfloat162float(h0), __bfloat162float(h1));
    hw.y = packbf(__bfloat162float(h2), __bfloat162float(h3));
    lw.x = packbf(l0, l1);
    lw.y = packbf(l2, l3);
    *(uint2*)(g_nhi + i4 * 4) = hw;
    *(uint2*)(g_nlo + i4 * 4) = lw;
}

// ---------------------------------------------------------------------------
// qterm[b, d] = b1[d] + sum_c q_feats[b, c] * W1q[d, c]
// ---------------------------------------------------------------------------
__global__ void qterm_kernel(const float* __restrict__ q_feats, const float* __restrict__ b1) {
    __shared__ __align__(16) float w[QD];
    int d = blockIdx.x;
    for (int i = threadIdx.x; i < QD; i += blockDim.x) w[i] = g_W1q[(size_t)d * QD + i];
    __syncthreads();
    int wid = threadIdx.x >> 5, lane = threadIdx.x & 31;
    float bias = b1[d];
    for (int b = wid; b < B_; b += 8) {
        const float* q = q_feats + (size_t)b * QD;
        float s = 0.f;
        for (int c = lane; c < QD; c += 32) s = fmaf(w[c], q[c], s);
        for (int o = 16; o; o >>= 1) s += __shfl_down_sync(0xFFFFFFFFu, s, o);
        if (lane == 0) g_qterm[(size_t)b * QD + d] = s + bias;
    }
}

// ---------------------------------------------------------------------------
// bf16x3 mma.sync NT GEMM: C[m,n] = sum_k A[m,k] * B[n,k]  (fp32 accum)
// CTA tile 128x128, BK=16, 8 warps (2Mx4N), warp tile 64x32.
// Double-buffered cp.async smem, ldmatrix fragment loads.
// smem rows: 24 bf16 (48B) stride -> conflict-free LDSM (3*row+q mod 8 distinct).
// MODE 1: A=node hi/lo, B=W1 hi/lo (K=2048), epi relu(+qterm) -> h1 hi/lo
// MODE 2: A=h1 hi/lo,  B=W2 hi/lo (K=1024), epi relu(+b2)    -> h2 hi/lo
// MODE 0: per-batch z: A=B=h2[z] (K=1024), epi fp32 -> g_S
// ---------------------------------------------------------------------------
#define SROW 24   // bf16 elements per smem row (16 data + 8 pad)

template <int MODE>
__global__ void __launch_bounds__(256, 1) bf3_gemm(const float* __restrict__ bias) {
    constexpr int K   = (MODE == 1) ? OBJ : QD;
    constexpr int NIT = K / 16;
    constexpr size_t ldk = (MODE == 1) ? OBJ : QD;

    // [stage][tensor: Ahi,Alo,Bhi,Blo][128 rows * 24 bf16]  = 48 KB total
    __shared__ __align__(16) __nv_bfloat16 sm[2][4][128 * SROW];

    const int tid  = threadIdx.x;
    const int wid  = tid >> 5;
    const int lane = tid & 31;
    const int wm   = wid >> 2;            // 0..1
    const int wn   = wid & 3;             // 0..3
    const int gr   = lane >> 2;           // 0..7
    const int ct   = lane & 3;            // 0..3
    const int m0   = blockIdx.y * 128;
    const int n0   = blockIdx.x * 128;

    const __nv_bfloat16 *Ahi, *Alo, *Bhi, *Blo;
    if (MODE == 1)      { Ahi = g_nhi;  Alo = g_nlo;  Bhi = g_W1hi; Blo = g_W1lo; }
    else if (MODE == 2) { Ahi = g_h1hi; Alo = g_h1lo; Bhi = g_W2hi; Blo = g_W2lo; }
    else {
        size_t off = (size_t)blockIdx.z * ((size_t)N_ * QD);
        Ahi = g_h2hi + off; Alo = g_h2lo + off; Bhi = Ahi; Blo = Alo;
    }

    // ---- loader mapping: thread t -> row t>>1, 16B chunk q = t&1 -----------
    const int lrow = tid >> 1;
    const int lq   = tid & 1;
    const uint32_t ldst = (uint32_t)(lrow * SROW + lq * 8);   // element offset
    const __nv_bfloat16* gA_hi = Ahi + (size_t)(m0 + lrow) * ldk + lq * 8;
    const __nv_bfloat16* gA_lo = Alo + (size_t)(m0 + lrow) * ldk + lq * 8;
    const __nv_bfloat16* gB_hi = Bhi + (size_t)(n0 + lrow) * ldk + lq * 8;
    const __nv_bfloat16* gB_lo = Blo + (size_t)(n0 + lrow) * ldk + lq * 8;

    uint32_t sbase[2][4];
#pragma unroll
    for (int s = 0; s < 2; s++)
#pragma unroll
        for (int t = 0; t < 4; t++) sbase[s][t] = smem_u32(&sm[s][t][0]);

    auto issue = [&](int it, int st) {
        const size_t k0 = (size_t)it * 16;
        cp16(sbase[st][0] + ldst * 2, gA_hi + k0);
        cp16(sbase[st][1] + ldst * 2, gA_lo + k0);
        cp16(sbase[st][2] + ldst * 2, gB_hi + k0);
        cp16(sbase[st][3] + ldst * 2, gB_lo + k0);
        cp_commit();
    };

    // ---- ldmatrix per-lane byte offsets ------------------------------------
    // A .x4 for m-tile mt: matrices {rows+0..7 k0-7, rows+8..15 k0-7,
    //                                rows+0..7 k8-15, rows+8..15 k8-15}
    const int lg = lane >> 3, lr = lane & 7;
    uint32_t aoff[4], boff[2];
#pragma unroll
    for (int mt = 0; mt < 4; mt++) {
        int row = wm * 64 + mt * 16 + (lg & 1) * 8 + lr;
        int q   = lg >> 1;
        aoff[mt] = (uint32_t)((row * SROW + q * 8) * 2);
    }
    // B .x4 for n-tile pair p: matrices {nt=2p k0-7, nt=2p k8-15,
    //                                    nt=2p+1 k0-7, nt=2p+1 k8-15}
#pragma unroll
    for (int p = 0; p < 2; p++) {
        int row = wn * 32 + (2 * p + (lg >> 1)) * 8 + lr;
        int q   = lg & 1;
        boff[p] = (uint32_t)((row * SROW + q * 8) * 2);
    }

    float acc[4][4][4];
#pragma unroll
    for (int i = 0; i < 4; i++)
#pragma unroll
        for (int j = 0; j < 4; j++)
#pragma unroll
            for (int r = 0; r < 4; r++) acc[i][j][r] = 0.f;

    issue(0, 0);

    for (int it = 0; it < NIT; ++it) {
        const int st = it & 1;
        if (it + 1 < NIT) { issue(it + 1, st ^ 1); cp_wait<1>(); }
        else              { cp_wait<0>(); }
        __syncthreads();

        uint32_t ah[4][4], al[4][4], bh[4][2], bl[4][2];
#pragma unroll
        for (int mt = 0; mt < 4; mt++) {
            ldsm4(ah[mt], sbase[st][0] + aoff[mt]);
            ldsm4(al[mt], sbase[st][1] + aoff[mt]);
        }
#pragma unroll
        for (int p = 0; p < 2; p++) {
            uint32_t t[4];
            ldsm4(t, sbase[st][2] + boff[p]);
            bh[2 * p][0] = t[0]; bh[2 * p][1] = t[1];
            bh[2 * p + 1][0] = t[2]; bh[2 * p + 1][1] = t[3];
            ldsm4(t, sbase[st][3] + boff[p]);
            bl[2 * p][0] = t[0]; bl[2 * p][1] = t[1];
            bl[2 * p + 1][0] = t[2]; bl[2 * p + 1][1] = t[3];
        }
#pragma unroll
        for (int mt = 0; mt < 4; mt++)
#pragma unroll
            for (int nt = 0; nt < 4; nt++) {
                mma_bf16(acc[mt][nt], ah[mt], bh[nt]);
                mma_bf16(acc[mt][nt], ah[mt], bl[nt]);
                mma_bf16(acc[mt][nt], al[mt], bh[nt]);
            }
        __syncthreads();
    }

    // ---- epilogue -----------------------------------------------------------
#pragma unroll
    for (int mt = 0; mt < 4; mt++) {
        int row_a = m0 + wm * 64 + mt * 16 + gr;
#pragma unroll
        for (int nt = 0; nt < 4; nt++) {
            int col = n0 + wn * 32 + nt * 8 + 2 * ct;
            float v0 = acc[mt][nt][0], v1 = acc[mt][nt][1];
            float v2 = acc[mt][nt][2], v3 = acc[mt][nt][3];
            if (MODE == 0) {
                float* dst = g_S + (size_t)blockIdx.z * ((size_t)N_ * N_);
                *(float2*)(dst + (size_t)row_a * N_ + col)       = make_float2(v0, v1);
                *(float2*)(dst + (size_t)(row_a + 8) * N_ + col) = make_float2(v2, v3);
            } else {
                const float* bsrc = (MODE == 1) ? (g_qterm + (size_t)(row_a >> 9) * QD) : bias;
                float b0 = bsrc[col], b1v = bsrc[col + 1];
                v0 = fmaxf(v0 + b0, 0.f);  v1 = fmaxf(v1 + b1v, 0.f);
                v2 = fmaxf(v2 + b0, 0.f);  v3 = fmaxf(v3 + b1v, 0.f);
                __nv_bfloat16* dh = (MODE == 1) ? g_h1hi : g_h2hi;
                __nv_bfloat16* dl = (MODE == 1) ? g_h1lo : g_h2lo;
                float h0 = __bfloat162float(__float2bfloat16(v0));
                float h1 = __bfloat162float(__float2bfloat16(v1));
                float h2 = __bfloat162float(__float2bfloat16(v2));
                float h3 = __bfloat162float(__float2bfloat16(v3));
                *(uint32_t*)(dh + (size_t)row_a * QD + col)       = packbf(h0, h1);
                *(uint32_t*)(dl + (size_t)row_a * QD + col)       = packbf(v0 - h0, v1 - h1);
                *(uint32_t*)(dh + (size_t)(row_a + 8) * QD + col) = packbf(h2, h3);
                *(uint32_t*)(dl + (size_t)(row_a + 8) * QD + col) = packbf(v2 - h2, v3 - h3);
            }
        }
    }
}

// ---------------------------------------------------------------------------
// Gather
// ---------------------------------------------------------------------------
__global__ void gather_kernel(const void* __restrict__ idx, float* __restrict__ out, int n) {
    int e = blockIdx.x * blockDim.x + threadIdx.x;
    if (e >= n) return;
    bool is64 = (g_odd_or == 0u);
    long long v = is64 ? ((const long long*)idx)[e] : (long long)((const int*)idx)[e];
    if (v < 0) v = 0;
    if (v >= (long long)STOT) v = (long long)STOT - 1;
    out[e] = g_S[v];
}

// ---------------------------------------------------------------------------
// Host entry (graph-capturable: kernel launches only)
// ---------------------------------------------------------------------------
extern "C" void kernel_launch(void* const* d_in, const int* in_sizes, int n_in,
                              void* d_out, int out_size) {
    const float* node = (const float*)d_in[0];
    const float* qf   = (const float*)d_in[1];
    const void*  idx  = d_in[2];
    const float* v1   = (const float*)d_in[3];
    const float* g1   = (const float*)d_in[4];
    const float* b1   = (const float*)d_in[5];
    const float* v2   = (const float*)d_in[6];
    const float* g2   = (const float*)d_in[7];
    const float* b2   = (const float*)d_in[8];
    float*       out  = (float*)d_out;

    (void)n_in; (void)in_sizes;

    zero_flag_kernel<<<1, 1>>>();                                    // 0
    detect_kernel<<<128, 256>>>((const unsigned int*)idx, out_size); // 1
    wn_kernel<<<2 * QD, 256>>>(v1, g1, v2, g2);                      // 2
    node_cvt_kernel<<<(MTOT * (OBJ / 4)) / 256, 256>>>(node);        // 3
    qterm_kernel<<<QD, 256>>>(qf, b1);                               // 4

    // 5: GEMM1  h1 = relu(node @ W1a^T + qterm)   (ncu -s 5 lands here)
    bf3_gemm<1><<<dim3(QD / 128, MTOT / 128), 256>>>(nullptr);
    // 6: GEMM2  h2 = relu(h1 @ W2^T + b2)
    bf3_gemm<2><<<dim3(QD / 128, MTOT / 128), 256>>>(b2);
    // 7: GEMM3  S[b] = h2[b] @ h2[b]^T
    bf3_gemm<0><<<dim3(N_ / 128, N_ / 128, B_), 256>>>(nullptr);

    gather_kernel<<<(out_size + 255) / 256, 256>>>(idx, out, out_size);
}

// round 7
// speedup vs baseline: 3.0991x; 1.6188x over previous
#include <cuda_runtime.h>
#include <cuda_bf16.h>
#include <cstdint>

// ---------------------------------------------------------------------------
// Problem constants
// ---------------------------------------------------------------------------
#define B_    32
#define N_    512
#define OBJ   2048
#define QD    1024
#define CD    3072
#define MTOT  16384
#define STOT  ((size_t)B_ * N_ * N_)

// ---------------------------------------------------------------------------
// Device scratch (static; no runtime allocation)
// ---------------------------------------------------------------------------
__device__ __align__(16) __nv_bfloat16 g_W1hi[(size_t)QD * OBJ];
__device__ __align__(16) float         g_W1q [(size_t)QD * QD];
__device__ __align__(16) __nv_bfloat16 g_W2hi[(size_t)QD * QD];
__device__ __align__(16) __nv_bfloat16 g_nhi [(size_t)MTOT * OBJ];
__device__ __align__(16) __nv_bfloat16 g_nlo [(size_t)MTOT * OBJ];
__device__ __align__(16) __nv_bfloat16 g_h1hi[(size_t)MTOT * QD];
__device__ __align__(16) __nv_bfloat16 g_h1lo[(size_t)MTOT * QD];
__device__ __align__(16) __nv_bfloat16 g_h2hi[(size_t)MTOT * QD];
__device__ __align__(16) __nv_bfloat16 g_h2lo[(size_t)MTOT * QD];
__device__ __align__(16) float g_S[STOT];
__device__ __align__(16) float g_qterm[B_ * QD];
__device__ unsigned int g_odd_or;

// ---------------------------------------------------------------------------
// helpers
// ---------------------------------------------------------------------------
__device__ __forceinline__ uint32_t smem_u32(const void* p) {
    uint32_t a;
    asm("{ .reg .u64 t; cvta.to.shared.u64 t, %1; cvt.u32.u64 %0, t; }" : "=r"(a) : "l"(p));
    return a;
}
__device__ __forceinline__ void cp16(uint32_t dst, const void* src) {
    asm volatile("cp.async.ca.shared.global [%0], [%1], 16;" :: "r"(dst), "l"(src) : "memory");
}
__device__ __forceinline__ void cp_commit() {
    asm volatile("cp.async.commit_group;" ::: "memory");
}
template <int N>
__device__ __forceinline__ void cp_wait() {
    asm volatile("cp.async.wait_group %0;" :: "n"(N) : "memory");
}
__device__ __forceinline__ void ldsm4(uint32_t* r, uint32_t addr) {
    asm volatile("ldmatrix.sync.aligned.m8n8.x4.shared.b16 {%0,%1,%2,%3}, [%4];"
                 : "=r"(r[0]), "=r"(r[1]), "=r"(r[2]), "=r"(r[3]) : "r"(addr));
}
__device__ __forceinline__ void mma_bf16(float* c, const uint32_t* a, const uint32_t* b) {
    asm volatile(
        "mma.sync.aligned.m16n8k16.row.col.f32.bf16.bf16.f32 "
        "{%0,%1,%2,%3}, {%4,%5,%6,%7}, {%8,%9}, {%0,%1,%2,%3};"
        : "+f"(c[0]), "+f"(c[1]), "+f"(c[2]), "+f"(c[3])
        : "r"(a[0]), "r"(a[1]), "r"(a[2]), "r"(a[3]), "r"(b[0]), "r"(b[1]));
}
__device__ __forceinline__ uint32_t packbf(float lo_elem, float hi_elem) {
    uint32_t w;
    asm("cvt.rn.bf16x2.f32 %0, %1, %2;" : "=r"(w) : "f"(hi_elem), "f"(lo_elem));
    return w;
}

// ---------------------------------------------------------------------------
// Index-dtype detection (indexes may be int32 or int64; values < 2^23)
// ---------------------------------------------------------------------------
__global__ void zero_flag_kernel() { g_odd_or = 0u; }

__global__ void detect_kernel(const unsigned int* __restrict__ w, int n_words) {
    int i = blockIdx.x * blockDim.x + threadIdx.x;
    unsigned int v = 0u;
    for (int p = 2 * i + 1; p < n_words; p += 2 * gridDim.x * blockDim.x) v |= w[p];
    for (int o = 16; o; o >>= 1) v |= __shfl_down_sync(0xFFFFFFFFu, v, o);
    if ((threadIdx.x & 31) == 0 && v) atomicOr(&g_odd_or, v);
}

// ---------------------------------------------------------------------------
// Weight norm: W1 node-part -> bf16 hi, W1 q-part -> fp32, W2 -> bf16 hi
// ---------------------------------------------------------------------------
__global__ void wn_kernel(const float* __restrict__ v1, const float* __restrict__ g1,
                          const float* __restrict__ v2, const float* __restrict__ g2) {
    int r = blockIdx.x;
    const float* src;
    int len;
    float g;
    if (r < QD) { src = v1 + (size_t)r * CD; len = CD; g = g1[r]; }
    else        { src = v2 + (size_t)(r - QD) * QD; len = QD; g = g2[r - QD]; }

    float s = 0.f;
    for (int i = threadIdx.x; i < len; i += blockDim.x) { float x = src[i]; s += x * x; }

    __shared__ float red[32];
    for (int o = 16; o; o >>= 1) s += __shfl_down_sync(0xFFFFFFFFu, s, o);
    if ((threadIdx.x & 31) == 0) red[threadIdx.x >> 5] = s;
    __syncthreads();
    if (threadIdx.x < 32) {
        float t = (threadIdx.x < (blockDim.x >> 5)) ? red[threadIdx.x] : 0.f;
        for (int o = 16; o; o >>= 1) t += __shfl_down_sync(0xFFFFFFFFu, t, o);
        if (threadIdx.x == 0) red[0] = rsqrtf(t);
    }
    __syncthreads();
    float scale = g * red[0];

    if (r < QD) {
        for (int i = threadIdx.x; i < CD; i += blockDim.x) {
            float x = src[i] * scale;
            if (i < OBJ) g_W1hi[(size_t)r * OBJ + i] = __float2bfloat16(x);
            else         g_W1q[(size_t)r * QD + (i - OBJ)] = x;
        }
    } else {
        int rr = r - QD;
        for (int i = threadIdx.x; i < QD; i += blockDim.x)
            g_W2hi[(size_t)rr * QD + i] = __float2bfloat16(src[i] * scale);
    }
}

// ---------------------------------------------------------------------------
// node_feats fp32 -> bf16 hi/lo split
// ---------------------------------------------------------------------------
__global__ void node_cvt_kernel(const float* __restrict__ node) {
    size_t i4 = (size_t)blockIdx.x * blockDim.x + threadIdx.x;
    float4 v = *(const float4*)(node + i4 * 4);
    __nv_bfloat16 h0 = __float2bfloat16(v.x), h1 = __float2bfloat16(v.y);
    __nv_bfloat16 h2 = __float2bfloat16(v.z), h3 = __float2bfloat16(v.w);
    uint2 hw, lw;
    hw.x = packbf(__bfloat162float(h0), __bfloat162float(h1));
    hw.y = packbf(__bfloat162float(h2), __bfloat162float(h3));
    lw.x = packbf(v.x - __bfloat162float(h0), v.y - __bfloat162float(h1));
    lw.y = packbf(v.z - __bfloat162float(h2), v.w - __bfloat162float(h3));
    *(uint2*)(g_nhi + i4 * 4) = hw;
    *(uint2*)(g_nlo + i4 * 4) = lw;
}

// ---------------------------------------------------------------------------
// qterm[b, d] = b1[d] + sum_c q_feats[b, c] * W1q[d, c]
// ---------------------------------------------------------------------------
__global__ void qterm_kernel(const float* __restrict__ q_feats, const float* __restrict__ b1) {
    __shared__ __align__(16) float w[QD];
    int d = blockIdx.x;
    for (int i = threadIdx.x; i < QD; i += blockDim.x) w[i] = g_W1q[(size_t)d * QD + i];
    __syncthreads();
    int wid = threadIdx.x >> 5, lane = threadIdx.x & 31;
    float bias = b1[d];
    for (int b = wid; b < B_; b += 8) {
        const float* q = q_feats + (size_t)b * QD;
        float s = 0.f;
        for (int c = lane; c < QD; c += 32) s = fmaf(w[c], q[c], s);
        for (int o = 16; o; o >>= 1) s += __shfl_down_sync(0xFFFFFFFFu, s, o);
        if (lane == 0) g_qterm[(size_t)b * QD + d] = s + bias;
    }
}

// ---------------------------------------------------------------------------
// 2-term bf16 NT GEMM: C = (Ahi + Alo) @ Bhi^T  (fp32 accum)
// CTA tile 128(M) x 256(N), BK=16, 8 warps (2M x 4N), warp tile 64x64.
// 4-stage cp.async pipeline, one __syncthreads per iter, ldmatrix frags.
// smem row stride 24 bf16 (48B) -> conflict-free LDSM.
// MODE 1: A=node hi/lo, B=W1 hi (K=2048), epi relu(+qterm) -> h1 hi/lo
// MODE 2: A=h1 hi/lo,  B=W2 hi (K=1024), epi relu(+b2)    -> h2 hi/lo
// MODE 0: per-batch z: A=h2[z] hi/lo, B=h2[z] hi (K=1024), epi fp32 -> g_S
// ---------------------------------------------------------------------------
#define SROW      24
#define OFF_AHI   0
#define OFF_ALO   (128 * SROW)              // 3072 elems
#define OFF_BHI   (2 * 128 * SROW)          // 6144 elems
#define SSTAGE    (OFF_BHI + 256 * SROW)    // 12288 elems = 24576 B
#define NSTAGE    4
#define GEMM_SMEM (NSTAGE * SSTAGE * 2)     // 98304 B

template <int MODE>
__global__ void __launch_bounds__(256, 1) bf2_gemm(const float* __restrict__ bias) {
    constexpr int K   = (MODE == 1) ? OBJ : QD;
    constexpr int NIT = K / 16;
    constexpr size_t ldk = (MODE == 1) ? OBJ : QD;

    extern __shared__ __align__(16) __nv_bfloat16 dsm[];
    const uint32_t sb = smem_u32(dsm);

    const int tid  = threadIdx.x;
    const int wid  = tid >> 5;
    const int lane = tid & 31;
    const int wm   = wid >> 2;            // 0..1  (64 M-rows)
    const int wn   = wid & 3;             // 0..3  (64 N-cols)
    const int gr   = lane >> 2;           // 0..7
    const int ct   = lane & 3;            // 0..3
    const int m0   = blockIdx.y * 128;
    const int n0   = blockIdx.x * 256;

    const __nv_bfloat16 *Ahi, *Alo, *Bhi;
    if (MODE == 1)      { Ahi = g_nhi;  Alo = g_nlo;  Bhi = g_W1hi; }
    else if (MODE == 2) { Ahi = g_h1hi; Alo = g_h1lo; Bhi = g_W2hi; }
    else {
        size_t off = (size_t)blockIdx.z * ((size_t)N_ * QD);
        Ahi = g_h2hi + off; Alo = g_h2lo + off; Bhi = g_h2hi + off;
    }

    // loader: A -> thread t: row t>>1, chunk t&1 (hi+lo); B -> row t, 2 chunks
    const int arow = tid >> 1, aq = tid & 1;
    const __nv_bfloat16* gAh = Ahi + (size_t)(m0 + arow) * ldk + aq * 8;
    const __nv_bfloat16* gAl = Alo + (size_t)(m0 + arow) * ldk + aq * 8;
    const __nv_bfloat16* gB  = Bhi + (size_t)(n0 + tid) * ldk;
    const uint32_t dA  = (uint32_t)((OFF_AHI + arow * SROW + aq * 8) * 2);
    const uint32_t dAl = (uint32_t)((OFF_ALO + arow * SROW + aq * 8) * 2);
    const uint32_t dB  = (uint32_t)((OFF_BHI + tid * SROW) * 2);

    auto issue = [&](int it) {
        const uint32_t s0 = sb + (uint32_t)((it & (NSTAGE - 1)) * SSTAGE * 2);
        const size_t k0 = (size_t)it * 16;
        cp16(s0 + dA,       gAh + k0);
        cp16(s0 + dAl,      gAl + k0);
        cp16(s0 + dB,       gB + k0);
        cp16(s0 + dB + 16,  gB + k0 + 8);
    };

    // ldmatrix byte offsets (relative to stage base)
    const int lg = lane >> 3, lr = lane & 7;
    uint32_t aoffb[4], boffb[4];
#pragma unroll
    for (int mt = 0; mt < 4; mt++) {
        int row = wm * 64 + mt * 16 + (lg & 1) * 8 + lr;
        int q   = lg >> 1;
        aoffb[mt] = (uint32_t)((OFF_AHI + row * SROW + q * 8) * 2);
    }
#pragma unroll
    for (int p = 0; p < 4; p++) {
        int row = wn * 64 + (2 * p + (lg >> 1)) * 8 + lr;
        int q   = lg & 1;
        boffb[p] = (uint32_t)((OFF_BHI + row * SROW + q * 8) * 2);
    }
    const uint32_t lo_delta = (uint32_t)((OFF_ALO - OFF_AHI) * 2);

    float acc[4][8][4];
#pragma unroll
    for (int i = 0; i < 4; i++)
#pragma unroll
        for (int j = 0; j < 8; j++)
#pragma unroll
            for (int r = 0; r < 4; r++) acc[i][j][r] = 0.f;

    // prologue: 3 stages in flight
    issue(0); cp_commit();
    issue(1); cp_commit();
    issue(2); cp_commit();

    for (int it = 0; it < NIT; ++it) {
        cp_wait<2>();
        __syncthreads();
        if (it + 3 < NIT) issue(it + 3);
        cp_commit();

        const uint32_t base = sb + (uint32_t)((it & (NSTAGE - 1)) * SSTAGE * 2);
        uint32_t ah[4][4], al[4][4];
#pragma unroll
        for (int mt = 0; mt < 4; mt++) {
            ldsm4(ah[mt], base + aoffb[mt]);
            ldsm4(al[mt], base + aoffb[mt] + lo_delta);
        }
#pragma unroll
        for (int p = 0; p < 4; p++) {
            uint32_t bt[4];
            ldsm4(bt, base + boffb[p]);
#pragma unroll
            for (int mt = 0; mt < 4; mt++) {
                mma_bf16(acc[mt][2 * p],     ah[mt], bt);
                mma_bf16(acc[mt][2 * p + 1], ah[mt], bt + 2);
            }
#pragma unroll
            for (int mt = 0; mt < 4; mt++) {
                mma_bf16(acc[mt][2 * p],     al[mt], bt);
                mma_bf16(acc[mt][2 * p + 1], al[mt], bt + 2);
            }
        }
    }
    // note: no trailing sync needed; each thread's data deps are satisfied

    // ---- epilogue -----------------------------------------------------------
#pragma unroll
    for (int mt = 0; mt < 4; mt++) {
        int row_a = m0 + wm * 64 + mt * 16 + gr;
#pragma unroll
        for (int nt = 0; nt < 8; nt++) {
            int col = n0 + wn * 64 + nt * 8 + 2 * ct;
            float v0 = acc[mt][nt][0], v1 = acc[mt][nt][1];
            float v2 = acc[mt][nt][2], v3 = acc[mt][nt][3];
            if (MODE == 0) {
                float* dst = g_S + (size_t)blockIdx.z * ((size_t)N_ * N_);
                *(float2*)(dst + (size_t)row_a * N_ + col)       = make_float2(v0, v1);
                *(float2*)(dst + (size_t)(row_a + 8) * N_ + col) = make_float2(v2, v3);
            } else {
                const float* bsrc = (MODE == 1) ? (g_qterm + (size_t)(row_a >> 9) * QD) : bias;
                float b0 = bsrc[col], b1v = bsrc[col + 1];
                v0 = fmaxf(v0 + b0, 0.f);  v1 = fmaxf(v1 + b1v, 0.f);
                v2 = fmaxf(v2 + b0, 0.f);  v3 = fmaxf(v3 + b1v, 0.f);
                __nv_bfloat16* dh = (MODE == 1) ? g_h1hi : g_h2hi;
                __nv_bfloat16* dl = (MODE == 1) ? g_h1lo : g_h2lo;
                float h0 = __bfloat162float(__float2bfloat16(v0));
                float h1 = __bfloat162float(__float2bfloat16(v1));
                float h2 = __bfloat162float(__float2bfloat16(v2));
                float h3 = __bfloat162float(__float2bfloat16(v3));
                *(uint32_t*)(dh + (size_t)row_a * QD + col)       = packbf(h0, h1);
                *(uint32_t*)(dl + (size_t)row_a * QD + col)       = packbf(v0 - h0, v1 - h1);
                *(uint32_t*)(dh + (size_t)(row_a + 8) * QD + col) = packbf(h2, h3);
                *(uint32_t*)(dl + (size_t)(row_a + 8) * QD + col) = packbf(v2 - h2, v3 - h3);
            }
        }
    }
}

// ---------------------------------------------------------------------------
// Gather
// ---------------------------------------------------------------------------
__global__ void gather_kernel(const void* __restrict__ idx, float* __restrict__ out, int n) {
    int e = blockIdx.x * blockDim.x + threadIdx.x;
    if (e >= n) return;
    bool is64 = (g_odd_or == 0u);
    long long v = is64 ? ((const long long*)idx)[e] : (long long)((const int*)idx)[e];
    if (v < 0) v = 0;
    if (v >= (long long)STOT) v = (long long)STOT - 1;
    out[e] = g_S[v];
}

// ---------------------------------------------------------------------------
// Host entry (graph-capturable: kernel launches only)
// ---------------------------------------------------------------------------
extern "C" void kernel_launch(void* const* d_in, const int* in_sizes, int n_in,
                              void* d_out, int out_size) {
    const float* node = (const float*)d_in[0];
    const float* qf   = (const float*)d_in[1];
    const void*  idx  = d_in[2];
    const float* v1   = (const float*)d_in[3];
    const float* g1   = (const float*)d_in[4];
    const float* b1   = (const float*)d_in[5];
    const float* v2   = (const float*)d_in[6];
    const float* g2   = (const float*)d_in[7];
    const float* b2   = (const float*)d_in[8];
    float*       out  = (float*)d_out;

    (void)n_in; (void)in_sizes;

    static bool attr_done = false;
    if (!attr_done) {
        cudaFuncSetAttribute(bf2_gemm<1>, cudaFuncAttributeMaxDynamicSharedMemorySize, GEMM_SMEM);
        cudaFuncSetAttribute(bf2_gemm<2>, cudaFuncAttributeMaxDynamicSharedMemorySize, GEMM_SMEM);
        cudaFuncSetAttribute(bf2_gemm<0>, cudaFuncAttributeMaxDynamicSharedMemorySize, GEMM_SMEM);
        attr_done = true;
    }

    zero_flag_kernel<<<1, 1>>>();
    detect_kernel<<<128, 256>>>((const unsigned int*)idx, out_size);
    wn_kernel<<<2 * QD, 256>>>(v1, g1, v2, g2);
    node_cvt_kernel<<<(MTOT * (OBJ / 4)) / 256, 256>>>(node);
    qterm_kernel<<<QD, 256>>>(qf, b1);

    // GEMM1: h1 = relu(node @ W1a^T + qterm)
    bf2_gemm<1><<<dim3(QD / 256, MTOT / 128), 256, GEMM_SMEM>>>(nullptr);
    // GEMM2: h2 = relu(h1 @ W2^T + b2)
    bf2_gemm<2><<<dim3(QD / 256, MTOT / 128), 256, GEMM_SMEM>>>(b2);
    // GEMM3: S[b] = h2[b] @ h2[b]^T
    bf2_gemm<0><<<dim3(N_ / 256, N_ / 128, B_), 256, GEMM_SMEM>>>(nullptr);

    gather_kernel<<<(out_size + 255) / 256, 256>>>(idx, out, out_size);
}